// round 7
// baseline (speedup 1.0000x reference)
#include <cuda_runtime.h>

#define MODES 64
#define AUD   16
#define T     32768
#define F     4096
#define NC    513

// ---------------- device scratch ----------------
__device__ float  g_amp[AUD * MODES];
__device__ float  g_Ec[MODES * NC], g_Sc[MODES * NC], g_Cc[MODES * NC];
__device__ float  g_Ef[MODES * 64], g_Sf[MODES * 64], g_Cf[MODES * 64];
__device__ float  g_Ecp[MODES * 64], g_Efp[MODES * 64];   // e^{+d n} coarse/fine
__device__ float2 g_cum[8 * MODES * AUD];                 // amp-scaled lag-chunk prefix
__device__ float  g_dpart[AUD * F];                       // diagonal conv part

// ---------------- K1: params + trig/exp tables ----------------
__global__ void k_tables(const float* __restrict__ freq_linear,
                         const float* __restrict__ amp_value,
                         const float* __restrict__ alpha_params,
                         const float* __restrict__ beta_params)
{
    int m = blockIdx.x;
    int tid = threadIdx.x;          // 128
    __shared__ float s_a[64], s_aw[64], s_b[64], s_bw[64];
    __shared__ float s_d, s_w;

    const float la0 = logf(0.6f), la1 = logf(60.0f);
    const float lb0 = logf(2e-8f), lb1 = logf(2e-6f);

    if (tid < 64) {
        float frac = (float)tid / 63.0f;
        float va = expf(la0 + (la1 - la0) * frac);
        float vb = expf(lb0 + (lb1 - lb0) * frac);
        float spa = log1pf(expf(alpha_params[m * 64 + tid]));
        float spb = log1pf(expf(beta_params [m * 64 + tid]));
        s_a[tid] = spa * va; s_aw[tid] = spa;
        s_b[tid] = spb * vb; s_bw[tid] = spb;
    } else if (tid < 80) {
        int a = tid - 64;
        float x = amp_value[a * MODES + m];
        float s = 1.0f / (1.0f + expf(-x));
        g_amp[a * MODES + m] = 2.0f * expf(2.30258509299404568f * logf(s)) + 1e-7f;
    }
    __syncthreads();
    if (tid == 0) {
        float asum = 0.f, awsum = 0.f, bsum = 0.f, bwsum = 0.f;
        for (int b = 0; b < 64; b++) {
            asum += s_a[b]; awsum += s_aw[b];
            bsum += s_b[b]; bwsum += s_bw[b];
        }
        float alpha = asum / awsum, beta = bsum / bwsum;
        float f2pi = freq_linear[m] * 6.28318530717958647692f;
        float lbd  = f2pi * f2pi;
        float dr   = 0.5f * (alpha + beta * lbd);
        s_d = dr / 16000.0f;
        s_w = sqrtf(lbd - dr * dr) / 16000.0f;
    }
    __syncthreads();
    float d = s_d, w = s_w;
    for (int i = tid; i < NC; i += 128) {
        float n = (float)(i << 6);
        float s, c;
        sincosf(w * n, &s, &c);
        g_Ec[m * NC + i] = expf(-d * n);
        g_Sc[m * NC + i] = s;
        g_Cc[m * NC + i] = c;
    }
    if (tid < 64) {
        float n = (float)tid;
        float s, c;
        sincosf(w * n, &s, &c);
        g_Ef[m * 64 + tid] = expf(-d * n);
        g_Sf[m * 64 + tid] = s;
        g_Cf[m * 64 + tid] = c;
        g_Ecp[m * 64 + tid] = expf(d * (float)(tid << 6));
        g_Efp[m * 64 + tid] = expf(d * n);
    }
}

// ---------------- K2: [chunk partials + prefix, blocks 0..63] + [diag conv, 64..127] ----------------
__global__ void __launch_bounds__(256) k_mid(const float* __restrict__ forces)
{
    __shared__ float sm[3072];   // 12KB
    int b = blockIdx.x, tid = threadIdx.x;

    if (b < 64) {
        // one block per mode: loop 8 lag-chunks, stage Rc/Rs in smem, prefix in regs
        int m = b;
        float* sRc = sm;            // 512
        float* sRs = sm + 512;      // 512
        int wrp = tid >> 5, lane = tid & 31;
        int a0 = wrp * 2, a1 = a0 + 1;
        float am0 = g_amp[a0 * MODES + m];
        float am1 = g_amp[a1 * MODES + m];
        float pA0 = 0.f, pB0 = 0.f, pA1 = 0.f, pB1 = 0.f;

        for (int c = 0; c < 8; c++) {
            int k0 = c << 9;
            __syncthreads();
            // stage Rc/Rs for lags [k0, k0+512): e^{+d tau} * cos/sin(w tau)
            for (int i = tid; i < 512; i += 256) {
                int tau = k0 + i;
                int c2 = tau >> 6, r2 = tau & 63;
                float Ep = g_Ecp[m * 64 + c2] * g_Efp[m * 64 + r2];
                float Sc = g_Sc[m * NC + c2], Cc = g_Cc[m * NC + c2];
                float Sf = g_Sf[m * 64 + r2], Cf = g_Cf[m * 64 + r2];
                sRc[i] = Ep * (Cc * Cf - Sc * Sf);
                sRs[i] = Ep * (Sc * Cf + Cc * Sf);
            }
            __syncthreads();
            const float* f0 = forces + a0 * F + 4095 - k0;   // g[tau] = forces[4095-tau]
            const float* f1 = forces + a1 * F + 4095 - k0;
            float A0 = 0.f, B0 = 0.f, A1 = 0.f, B1 = 0.f;
            #pragma unroll 4
            for (int k = lane; k < 512; k += 32) {
                float rc = sRc[k], rs = sRs[k];
                float x0 = f0[-k], x1 = f1[-k];
                A0 = fmaf(x0, rc, A0); B0 = fmaf(x0, rs, B0);
                A1 = fmaf(x1, rc, A1); B1 = fmaf(x1, rs, B1);
            }
            #pragma unroll
            for (int o = 16; o; o >>= 1) {
                A0 += __shfl_xor_sync(0xffffffffu, A0, o);
                B0 += __shfl_xor_sync(0xffffffffu, B0, o);
                A1 += __shfl_xor_sync(0xffffffffu, A1, o);
                B1 += __shfl_xor_sync(0xffffffffu, B1, o);
            }
            pA0 += A0; pB0 += B0; pA1 += A1; pB1 += B1;
            if (lane == 0) {
                g_cum[c * 1024 + m * AUD + a0] = make_float2(am0 * pA0, am0 * pB0);
                g_cum[c * 1024 + m * AUD + a1] = make_float2(am1 * pA1, am1 * pB1);
            }
        }
    } else {
        // diagonal tile: out_diag[a][ti*512+u] = sum_k sfr[k]*shs2[u+k]
        //   sfr[k] = forces[3584 - ti*512 + k];  shs2[511+j] = s0[a][j] (recomputed here)
        int b2 = b - 64;                  // 0..63
        int ti = b2 >> 3, ap = b2 & 7;
        int half = tid >> 7;              // two audios per block
        int a = ap * 2 + half;
        int ltid = tid & 127;
        float* sfr  = sm + half * 1536;         // 512
        float* shs2 = sm + half * 1536 + 512;   // 1024

        for (int i = ltid; i < 512; i += 128)
            sfr[i] = forces[a * F + 3584 - (ti << 9) + i];

        const float* ampp = g_amp + a * MODES;
        for (int i = ltid; i < 1024; i += 128) {
            float v = 0.f;
            if (i >= 511 && i < 1023) {
                int j = i - 511;
                int n = j + 1, c = n >> 6, r = n & 63;
                #pragma unroll 4
                for (int m = 0; m < MODES; m++) {
                    float Ec = g_Ec[m * NC + c], Sc = g_Sc[m * NC + c], Cc = g_Cc[m * NC + c];
                    float Ef = g_Ef[m * 64 + r], Sf = g_Sf[m * 64 + r], Cf = g_Cf[m * 64 + r];
                    float ps = Ec * Ef * (Sc * Cf + Cc * Sf);
                    v = fmaf(ampp[m], ps, v);
                }
            }
            shs2[i] = v;
        }
        __syncthreads();

        int base = ltid * 4;
        float a0 = 0.f, a1 = 0.f, a2 = 0.f, a3 = 0.f;
        float4 sc = *(const float4*)(shs2 + base);
        #pragma unroll 4
        for (int k = 0; k < 512; k += 4) {
            float4 f4 = *(const float4*)(sfr + k);
            float4 sn = *(const float4*)(shs2 + base + k + 4);
            a0 = fmaf(f4.x, sc.x, a0); a1 = fmaf(f4.x, sc.y, a1); a2 = fmaf(f4.x, sc.z, a2); a3 = fmaf(f4.x, sc.w, a3);
            a0 = fmaf(f4.y, sc.y, a0); a1 = fmaf(f4.y, sc.z, a1); a2 = fmaf(f4.y, sc.w, a2); a3 = fmaf(f4.y, sn.x, a3);
            a0 = fmaf(f4.z, sc.z, a0); a1 = fmaf(f4.z, sc.w, a1); a2 = fmaf(f4.z, sn.x, a2); a3 = fmaf(f4.z, sn.y, a3);
            a0 = fmaf(f4.w, sc.w, a0); a1 = fmaf(f4.w, sn.x, a1); a2 = fmaf(f4.w, sn.y, a2); a3 = fmaf(f4.w, sn.z, a3);
            sc = sn;
        }
        float* dp = g_dpart + a * F + (ti << 9) + base;
        dp[0] = a0; dp[1] = a1; dp[2] = a2; dp[3] = a3;
    }
}

// ---------------- K3: output GEMM, ps/pc from tables inline ----------------
__global__ void __launch_bounds__(128) k_out(float* __restrict__ out)
{
    __shared__ float2 shc[MODES * AUD];
    int b = blockIdx.x, tid = threadIdx.x;
    int t = b * 128 + tid;
    int ti = b >> 2;
    int cc = ti < 8 ? ti : 8;

    float acc[AUD];
    #pragma unroll
    for (int a = 0; a < AUD; a++) acc[a] = 0.f;

    if (cc > 0) {
        for (int i = tid; i < MODES * AUD; i += 128)
            shc[i] = g_cum[(cc - 1) * 1024 + i];
        __syncthreads();
        int n = t + 1, c = n >> 6, r = n & 63;
        const float4* shc4 = (const float4*)shc;
        #pragma unroll 4
        for (int m = 0; m < MODES; m++) {
            float Ec = g_Ec[m * NC + c], Sc = g_Sc[m * NC + c], Cc = g_Cc[m * NC + c];
            float Ef = g_Ef[m * 64 + r], Sf = g_Sf[m * 64 + r], Cf = g_Cf[m * 64 + r];
            float E  = Ec * Ef;
            float ps = E * (Sc * Cf + Cc * Sf);
            float pc = E * (Cc * Cf - Sc * Sf);
            #pragma unroll
            for (int aa = 0; aa < 8; aa++) {
                float4 v = shc4[m * 8 + aa];
                acc[2 * aa]     = fmaf(ps, v.x, fmaf(-pc, v.y, acc[2 * aa]));
                acc[2 * aa + 1] = fmaf(ps, v.z, fmaf(-pc, v.w, acc[2 * aa + 1]));
            }
        }
    }
    if (ti < 8) {
        #pragma unroll
        for (int a = 0; a < AUD; a++)
            acc[a] += g_dpart[a * F + t];
    }
    #pragma unroll
    for (int a = 0; a < AUD; a++)
        out[a * T + t] = acc[a];
}

// ---------------- launch ----------------
extern "C" void kernel_launch(void* const* d_in, const int* in_sizes, int n_in,
                              void* d_out, int out_size)
{
    const float* freq   = (const float*)d_in[0];
    const float* ampv   = (const float*)d_in[1];
    const float* ap     = (const float*)d_in[2];
    const float* bp     = (const float*)d_in[3];
    const float* forces = (const float*)d_in[4];
    float* out = (float*)d_out;

    k_tables<<<MODES, 128>>>(freq, ampv, ap, bp);
    k_mid<<<128, 256>>>(forces);
    k_out<<<256, 128>>>(out);
}

// round 8
// speedup vs baseline: 1.3457x; 1.3457x over previous
#include <cuda_runtime.h>

#define MODES 64
#define AUD   16
#define T     32768
#define F     4096
#define NC    513

// ---------------- device scratch ----------------
__device__ float2 g_Fd[MODES * 64];    // (Ef*sin(w r), Ef*cos(w r)),  Ef = e^{-d r}
__device__ float2 g_Cd[MODES * NC];    // (Ec*sin(w 64c), Ec*cos(w 64c)), Ec = e^{-d 64c}
__device__ float2 g_Fg[MODES * 64];    // growth fine:  e^{+d r} * (sin, cos)
__device__ float2 g_Cg[MODES * 64];    // growth coarse: e^{+d 64c} * (sin, cos)
__device__ float  g_ampT[MODES * AUD]; // amp[m*16+a]
__device__ float2 g_ABp[8 * MODES * AUD]; // lag-chunk partials, [c][m*16+a]
__device__ float  g_dpart[AUD * F];       // diagonal conv part

// ---------------- K1: params + paired trig/exp tables ----------------
__global__ void k_tables(const float* __restrict__ freq_linear,
                         const float* __restrict__ amp_value,
                         const float* __restrict__ alpha_params,
                         const float* __restrict__ beta_params)
{
    int m = blockIdx.x;
    int tid = threadIdx.x;          // 128
    __shared__ float s_a[64], s_aw[64], s_b[64], s_bw[64];
    __shared__ float s_d, s_w;

    const float la0 = logf(0.6f), la1 = logf(60.0f);
    const float lb0 = logf(2e-8f), lb1 = logf(2e-6f);

    if (tid < 64) {
        float frac = (float)tid / 63.0f;
        float va = expf(la0 + (la1 - la0) * frac);
        float vb = expf(lb0 + (lb1 - lb0) * frac);
        float spa = log1pf(expf(alpha_params[m * 64 + tid]));
        float spb = log1pf(expf(beta_params [m * 64 + tid]));
        s_a[tid] = spa * va; s_aw[tid] = spa;
        s_b[tid] = spb * vb; s_bw[tid] = spb;
    } else if (tid < 80) {
        int a = tid - 64;
        float x = amp_value[a * MODES + m];
        float s = 1.0f / (1.0f + expf(-x));
        g_ampT[m * AUD + a] = 2.0f * expf(2.30258509299404568f * logf(s)) + 1e-7f;
    }
    __syncthreads();
    if (tid == 0) {
        float asum = 0.f, awsum = 0.f, bsum = 0.f, bwsum = 0.f;
        for (int b = 0; b < 64; b++) {
            asum += s_a[b]; awsum += s_aw[b];
            bsum += s_b[b]; bwsum += s_bw[b];
        }
        float alpha = asum / awsum, beta = bsum / bwsum;
        float f2pi = freq_linear[m] * 6.28318530717958647692f;
        float lbd  = f2pi * f2pi;
        float dr   = 0.5f * (alpha + beta * lbd);
        s_d = dr / 16000.0f;
        s_w = sqrtf(lbd - dr * dr) / 16000.0f;
    }
    __syncthreads();
    float d = s_d, w = s_w;
    for (int i = tid; i < NC; i += 128) {
        float n = (float)(i << 6);
        float s, c;
        sincosf(w * n, &s, &c);
        float Ec = expf(-d * n);
        g_Cd[m * NC + i] = make_float2(Ec * s, Ec * c);
        if (i < 64) {
            float Ecp = expf(d * n);
            g_Cg[m * 64 + i] = make_float2(Ecp * s, Ecp * c);
        }
    }
    if (tid < 64) {
        float n = (float)tid;
        float s, c;
        sincosf(w * n, &s, &c);
        float Ef  = expf(-d * n);
        float Efp = expf(d * n);
        g_Fd[m * 64 + tid] = make_float2(Ef * s, Ef * c);
        g_Fg[m * 64 + tid] = make_float2(Efp * s, Efp * c);
    }
}

// ---------------- K2: [lag-chunk partials 0..511] + [diag conv 512..639] ----------------
__global__ void __launch_bounds__(256) k_mid(const float* __restrict__ forces)
{
    __shared__ float sm[1536];   // 6KB
    int b = blockIdx.x, tid = threadIdx.x;

    if (b < 512) {
        // chunk partials: A[m][c] = sum_tau g[tau]*Rc[m][tau], g[tau]=forces[4095-tau]
        int m = b >> 3, cchunk = b & 7, k0 = cchunk << 9;
        float* sRc = sm;            // 512
        float* sRs = sm + 512;      // 512
        for (int i = tid; i < 512; i += 256) {
            int tau = k0 + i;
            float2 Fg = g_Fg[m * 64 + (tau & 63)];
            float2 Cg = g_Cg[m * 64 + (tau >> 6)];
            sRc[i] = Cg.y * Fg.y - Cg.x * Fg.x;   // e^{+d tau} cos(w tau)
            sRs[i] = Cg.x * Fg.y + Cg.y * Fg.x;   // e^{+d tau} sin(w tau)
        }
        __syncthreads();

        int wrp = tid >> 5, lane = tid & 31;
        int a0 = wrp * 2, a1 = a0 + 1;
        const float* f0 = forces + a0 * F + 4095 - k0;
        const float* f1 = forces + a1 * F + 4095 - k0;
        float A0 = 0.f, B0 = 0.f, A1 = 0.f, B1 = 0.f;
        #pragma unroll 4
        for (int k = lane; k < 512; k += 32) {
            float rc = sRc[k], rs = sRs[k];
            float x0 = f0[-k], x1 = f1[-k];
            A0 = fmaf(x0, rc, A0); B0 = fmaf(x0, rs, B0);
            A1 = fmaf(x1, rc, A1); B1 = fmaf(x1, rs, B1);
        }
        #pragma unroll
        for (int o = 16; o; o >>= 1) {
            A0 += __shfl_xor_sync(0xffffffffu, A0, o);
            B0 += __shfl_xor_sync(0xffffffffu, B0, o);
            A1 += __shfl_xor_sync(0xffffffffu, A1, o);
            B1 += __shfl_xor_sync(0xffffffffu, B1, o);
        }
        if (lane == 0) {
            g_ABp[cchunk * 1024 + m * AUD + a0] = make_float2(A0, B0);
            g_ABp[cchunk * 1024 + m * AUD + a1] = make_float2(A1, B1);
        }
    } else {
        // diagonal tile (ti, a): out[u] = sum_k sfr[k]*s0pad[u+k]
        int b2 = b - 512;                 // 0..127
        int ti = b2 >> 4, a = b2 & 15;
        float* s0pad = sm;                // 1024 (zeros | s0[0..511] | 0)
        float* sfr   = sm + 1024;         // 512

        // s0pad: index i in [511,1023) holds s0[i-511]
        for (int i = tid; i < 1024; i += 256) {
            float v = 0.f;
            if (i >= 511 && i < 1023) {
                int n = i - 510;          // j+1, j = i-511
                int c2 = n >> 6, r2 = n & 63;
                #pragma unroll 4
                for (int m = 0; m < MODES; m++) {
                    float2 Fd = g_Fd[m * 64 + r2];
                    float2 Cd = g_Cd[m * NC + c2];
                    float ps = Cd.x * Fd.y + Cd.y * Fd.x;
                    v = fmaf(g_ampT[m * AUD + a], ps, v);
                }
            }
            s0pad[i] = v;
        }
        for (int i = tid; i < 512; i += 256)
            sfr[i] = forces[a * F + 3584 - (ti << 9) + i];
        __syncthreads();

        int base = tid * 2;
        float acc0 = 0.f, acc1 = 0.f;
        float cur = s0pad[base];
        #pragma unroll 4
        for (int k = 0; k < 512; k += 4) {
            float4 f4 = *(const float4*)(sfr + k);
            float s1 = s0pad[base + k + 1];
            float s2 = s0pad[base + k + 2];
            float s3 = s0pad[base + k + 3];
            float s4 = s0pad[base + k + 4];
            acc0 = fmaf(f4.x, cur, acc0); acc1 = fmaf(f4.x, s1, acc1);
            acc0 = fmaf(f4.y, s1,  acc0); acc1 = fmaf(f4.y, s2, acc1);
            acc0 = fmaf(f4.z, s2,  acc0); acc1 = fmaf(f4.z, s3, acc1);
            acc0 = fmaf(f4.w, s3,  acc0); acc1 = fmaf(f4.w, s4, acc1);
            cur = s4;
        }
        float* dp = g_dpart + a * F + (ti << 9) + base;
        dp[0] = acc0; dp[1] = acc1;
    }
}

// ---------------- K3: output GEMM (prefix + tables inline) ----------------
__global__ void __launch_bounds__(128) k_out(float* __restrict__ out)
{
    __shared__ float2 shc[MODES * AUD];   // 8KB
    __shared__ float2 sFd[MODES * 64];    // 32KB
    int b = blockIdx.x, tid = threadIdx.x;
    int t = b * 128 + tid;
    int ti = b >> 2;
    int cc = ti < 8 ? ti : 8;

    float acc[AUD];
    #pragma unroll
    for (int a = 0; a < AUD; a++) acc[a] = 0.f;

    if (cc > 0) {
        // prefix over lag chunks, amp folded
        for (int i = tid; i < MODES * AUD; i += 128) {
            float A = 0.f, B = 0.f;
            for (int c = 0; c < cc; c++) {
                float2 p = g_ABp[c * 1024 + i];
                A += p.x; B += p.y;
            }
            float am = g_ampT[i];
            shc[i] = make_float2(am * A, am * B);
        }
        // stage fine tables
        for (int i = tid; i < MODES * 64; i += 128)
            sFd[i] = g_Fd[i];
        __syncthreads();

        int n = t + 1, c2 = n >> 6, r2 = n & 63;
        const float4* shc4 = (const float4*)shc;
        #pragma unroll 4
        for (int m = 0; m < MODES; m++) {
            float2 Fd = sFd[m * 64 + r2];
            float2 Cd = g_Cd[m * NC + c2];
            float ps  = Cd.x * Fd.y + Cd.y * Fd.x;
            float npc = Cd.x * Fd.x - Cd.y * Fd.y;   // -pc
            #pragma unroll
            for (int aa = 0; aa < 8; aa++) {
                float4 v = shc4[m * 8 + aa];
                acc[2 * aa]     = fmaf(ps, v.x, fmaf(npc, v.y, acc[2 * aa]));
                acc[2 * aa + 1] = fmaf(ps, v.z, fmaf(npc, v.w, acc[2 * aa + 1]));
            }
        }
    }
    if (ti < 8) {
        #pragma unroll
        for (int a = 0; a < AUD; a++)
            acc[a] += g_dpart[a * F + t];
    }
    #pragma unroll
    for (int a = 0; a < AUD; a++)
        out[a * T + t] = acc[a];
}

// ---------------- launch ----------------
extern "C" void kernel_launch(void* const* d_in, const int* in_sizes, int n_in,
                              void* d_out, int out_size)
{
    const float* freq   = (const float*)d_in[0];
    const float* ampv   = (const float*)d_in[1];
    const float* ap     = (const float*)d_in[2];
    const float* bp     = (const float*)d_in[3];
    const float* forces = (const float*)d_in[4];
    float* out = (float*)d_out;

    k_tables<<<MODES, 128>>>(freq, ampv, ap, bp);
    k_mid<<<640, 256>>>(forces);
    k_out<<<256, 128>>>(out);
}

// round 9
// speedup vs baseline: 1.9282x; 1.4329x over previous
#include <cuda_runtime.h>

#define MODES 64
#define AUD   16
#define T     32768
#define F     4096
#define NC    513
#define NB    128      // all blocks must be co-resident (1/SM, 128 < 148 SMs)

// ---------------- device scratch ----------------
__device__ float2 g_Fd[MODES * 64];    // decay fine:   e^{-d r}  * (sin, cos)(w r)
__device__ float2 g_Cd[MODES * NC];    // decay coarse: e^{-d 64c}* (sin, cos)(w 64c)
__device__ float2 g_Fg[MODES * 64];    // growth fine:  e^{+d r}  * (sin, cos)
__device__ float2 g_Cg[MODES * 64];    // growth coarse
__device__ float  g_ampT[MODES * AUD];
__device__ float2 g_cum[8 * MODES * AUD];   // amp-scaled lag-chunk prefix
__device__ float  g_dpart[AUD * F];         // diagonal conv part
__device__ unsigned g_count = 0;
__device__ unsigned g_gen   = 0;

// ---------------- software grid barrier (all NB blocks resident) ----------------
__device__ __forceinline__ void grid_bar()
{
    __syncthreads();
    if (threadIdx.x == 0) {
        unsigned gen = *(volatile unsigned*)&g_gen;
        __threadfence();
        if (atomicAdd(&g_count, 1u) == NB - 1) {
            g_count = 0;
            __threadfence();
            *(volatile unsigned*)&g_gen = gen + 1;
        } else {
            while (*(volatile unsigned*)&g_gen == gen) { }
        }
        __threadfence();
    }
    __syncthreads();
}

// ---------------- the one kernel ----------------
__global__ void __launch_bounds__(256) k_all(const float* __restrict__ freq_linear,
                                             const float* __restrict__ amp_value,
                                             const float* __restrict__ alpha_params,
                                             const float* __restrict__ beta_params,
                                             const float* __restrict__ forces,
                                             float* __restrict__ out)
{
    __shared__ float sm[10240];   // 40KB, re-carved per phase
    int b = blockIdx.x, tid = threadIdx.x;

    // ================= Phase A: per-mode params + paired tables =================
    if (b < MODES) {
        int m = b;
        float* s_a  = sm;        float* s_aw = sm + 64;
        float* s_b  = sm + 128;  float* s_bw = sm + 192;

        const float la0 = logf(0.6f), la1 = logf(60.0f);
        const float lb0 = logf(2e-8f), lb1 = logf(2e-6f);

        if (tid < 64) {
            float frac = (float)tid / 63.0f;
            float va = expf(la0 + (la1 - la0) * frac);
            float vb = expf(lb0 + (lb1 - lb0) * frac);
            float spa = log1pf(expf(alpha_params[m * 64 + tid]));
            float spb = log1pf(expf(beta_params [m * 64 + tid]));
            s_a[tid] = spa * va; s_aw[tid] = spa;
            s_b[tid] = spb * vb; s_bw[tid] = spb;
        } else if (tid < 80) {
            int a = tid - 64;
            float x = amp_value[a * MODES + m];
            float s = 1.0f / (1.0f + expf(-x));
            g_ampT[m * AUD + a] = 2.0f * expf(2.30258509299404568f * logf(s)) + 1e-7f;
        }
        __syncthreads();
        if (tid == 0) {
            float asum = 0.f, awsum = 0.f, bsum = 0.f, bwsum = 0.f;
            for (int i = 0; i < 64; i++) {
                asum += s_a[i]; awsum += s_aw[i];
                bsum += s_b[i]; bwsum += s_bw[i];
            }
            float alpha = asum / awsum, beta = bsum / bwsum;
            float f2pi = freq_linear[m] * 6.28318530717958647692f;
            float lbd  = f2pi * f2pi;
            float dr   = 0.5f * (alpha + beta * lbd);
            sm[256] = dr / 16000.0f;
            sm[257] = sqrtf(lbd - dr * dr) / 16000.0f;
        }
        __syncthreads();
        float d = sm[256], w = sm[257];
        for (int i = tid; i < NC; i += 256) {
            float n = (float)(i << 6);
            float s, c;
            sincosf(w * n, &s, &c);
            float Ec = expf(-d * n);
            g_Cd[m * NC + i] = make_float2(Ec * s, Ec * c);
            if (i < 64) {
                float Ep = expf(d * n);
                g_Cg[m * 64 + i] = make_float2(Ep * s, Ep * c);
            }
        }
        if (tid < 64) {
            float n = (float)tid;
            float s, c;
            sincosf(w * n, &s, &c);
            float Ef = expf(-d * n), Ep = expf(d * n);
            g_Fd[m * 64 + tid] = make_float2(Ef * s, Ef * c);
            g_Fg[m * 64 + tid] = make_float2(Ep * s, Ep * c);
        }
    }

    grid_bar();

    // ================= Phase B =================
    if (b < 64) {
        // ---- diagonal pair: units (ti, a0=even) and (ti, a0+1) ----
        int u0 = 2 * b;
        int ti = u0 >> 4;
        int a0 = u0 & 15, a1 = a0 + 1;
        float* sfr0 = sm;            // 512
        float* sfr1 = sm + 512;      // 512
        float* sp0  = sm + 1024;     // 1024
        float* sp1  = sm + 2048;     // 1024
        float* sam0 = sm + 3072;     // 64
        float* sam1 = sm + 3136;     // 64

        if (tid < 64)        sam0[tid]      = g_ampT[tid * AUD + a0];
        else if (tid < 128)  sam1[tid - 64] = g_ampT[(tid - 64) * AUD + a1];
        int fb = 3584 - (ti << 9);
        for (int i = tid; i < 512; i += 256) {
            sfr0[i] = forces[a0 * F + fb + i];
            sfr1[i] = forces[a1 * F + fb + i];
        }
        __syncthreads();

        // s0 for both audios, shared ps
        for (int i = tid; i < 1024; i += 256) {
            float v0 = 0.f, v1 = 0.f;
            if (i >= 511 && i < 1023) {
                int n = i - 510;            // j+1
                int c2 = n >> 6, r2 = n & 63;
                #pragma unroll 4
                for (int m = 0; m < MODES; m++) {
                    float2 Fd = g_Fd[m * 64 + r2];
                    float2 Cd = g_Cd[m * NC + c2];
                    float ps = Cd.x * Fd.y + Cd.y * Fd.x;
                    v0 = fmaf(sam0[m], ps, v0);
                    v1 = fmaf(sam1[m], ps, v1);
                }
            }
            sp0[i] = v0; sp1[i] = v1;
        }
        __syncthreads();

        int half = tid >> 7, ltid = tid & 127;
        float* sfr = half ? sfr1 : sfr0;
        float* sp  = half ? sp1  : sp0;
        int a = half ? a1 : a0;
        int base = ltid * 4;
        float c0 = 0.f, c1 = 0.f, c2a = 0.f, c3 = 0.f;
        float4 sc = *(const float4*)(sp + base);
        #pragma unroll 4
        for (int k = 0; k < 512; k += 4) {
            float4 f4 = *(const float4*)(sfr + k);
            float4 sn = *(const float4*)(sp + base + k + 4);
            c0 = fmaf(f4.x, sc.x, c0); c1 = fmaf(f4.x, sc.y, c1); c2a = fmaf(f4.x, sc.z, c2a); c3 = fmaf(f4.x, sc.w, c3);
            c0 = fmaf(f4.y, sc.y, c0); c1 = fmaf(f4.y, sc.z, c1); c2a = fmaf(f4.y, sc.w, c2a); c3 = fmaf(f4.y, sn.x, c3);
            c0 = fmaf(f4.z, sc.z, c0); c1 = fmaf(f4.z, sc.w, c1); c2a = fmaf(f4.z, sn.x, c2a); c3 = fmaf(f4.z, sn.y, c3);
            c0 = fmaf(f4.w, sc.w, c0); c1 = fmaf(f4.w, sn.x, c1); c2a = fmaf(f4.w, sn.y, c2a); c3 = fmaf(f4.w, sn.z, c3);
            sc = sn;
        }
        *(float4*)(g_dpart + a * F + (ti << 9) + base) = make_float4(c0, c1, c2a, c3);
    } else {
        // ---- one mode per block: 8 lag-chunks, prefix in registers ----
        int m = b - 64;
        float* sRc = sm;            // 512
        float* sRs = sm + 512;      // 512
        int wrp = tid >> 5, lane = tid & 31;
        int a0 = wrp * 2, a1 = a0 + 1;
        float am0 = g_ampT[m * AUD + a0];
        float am1 = g_ampT[m * AUD + a1];
        float pA0 = 0.f, pB0 = 0.f, pA1 = 0.f, pB1 = 0.f;

        for (int c = 0; c < 8; c++) {
            int k0 = c << 9;
            __syncthreads();
            for (int i = tid; i < 512; i += 256) {
                int tau = k0 + i;
                float2 Fg = g_Fg[m * 64 + (tau & 63)];
                float2 Cg = g_Cg[m * 64 + (tau >> 6)];
                sRc[i] = Cg.y * Fg.y - Cg.x * Fg.x;
                sRs[i] = Cg.x * Fg.y + Cg.y * Fg.x;
            }
            __syncthreads();
            const float* f0 = forces + a0 * F + 4095 - k0;
            const float* f1 = forces + a1 * F + 4095 - k0;
            float A0 = 0.f, B0 = 0.f, A1 = 0.f, B1 = 0.f;
            #pragma unroll 4
            for (int k = lane; k < 512; k += 32) {
                float rc = sRc[k], rs = sRs[k];
                float x0 = f0[-k], x1 = f1[-k];
                A0 = fmaf(x0, rc, A0); B0 = fmaf(x0, rs, B0);
                A1 = fmaf(x1, rc, A1); B1 = fmaf(x1, rs, B1);
            }
            #pragma unroll
            for (int o = 16; o; o >>= 1) {
                A0 += __shfl_xor_sync(0xffffffffu, A0, o);
                B0 += __shfl_xor_sync(0xffffffffu, B0, o);
                A1 += __shfl_xor_sync(0xffffffffu, A1, o);
                B1 += __shfl_xor_sync(0xffffffffu, B1, o);
            }
            pA0 += A0; pB0 += B0; pA1 += A1; pB1 += B1;
            if (lane == 0) {
                g_cum[c * 1024 + m * AUD + a0] = make_float2(am0 * pA0, am0 * pB0);
                g_cum[c * 1024 + m * AUD + a1] = make_float2(am1 * pA1, am1 * pB1);
            }
        }
    }

    grid_bar();

    // ================= Phase C: one 256-sample output tile per block =================
    {
        int tile = b;                    // 0..127
        int t = tile * 256 + tid;
        int cc = tile >> 1; if (cc > 8) cc = 8;

        float acc[AUD];
        #pragma unroll
        for (int a = 0; a < AUD; a++) acc[a] = 0.f;

        if (cc > 0) {
            float2* shc = (float2*)sm;             // 1024 float2
            float2* sFd = (float2*)(sm + 2048);    // 4096 float2
            for (int i = tid; i < MODES * AUD; i += 256)
                shc[i] = g_cum[(cc - 1) * 1024 + i];
            for (int i = tid; i < MODES * 64; i += 256)
                sFd[i] = g_Fd[i];
            __syncthreads();

            int n = t + 1, c2 = n >> 6, r2 = n & 63;
            const float4* shc4 = (const float4*)shc;
            #pragma unroll 4
            for (int m = 0; m < MODES; m++) {
                float2 Fd = sFd[m * 64 + r2];
                float2 Cd = g_Cd[m * NC + c2];
                float ps  = Cd.x * Fd.y + Cd.y * Fd.x;
                float npc = Cd.x * Fd.x - Cd.y * Fd.y;   // -pc
                #pragma unroll
                for (int aa = 0; aa < 8; aa++) {
                    float4 v = shc4[m * 8 + aa];
                    acc[2 * aa]     = fmaf(ps, v.x, fmaf(npc, v.y, acc[2 * aa]));
                    acc[2 * aa + 1] = fmaf(ps, v.z, fmaf(npc, v.w, acc[2 * aa + 1]));
                }
            }
        }
        if (t < F) {
            #pragma unroll
            for (int a = 0; a < AUD; a++)
                acc[a] += g_dpart[a * F + t];
        }
        #pragma unroll
        for (int a = 0; a < AUD; a++)
            out[a * T + t] = acc[a];
    }
}

// ---------------- launch ----------------
extern "C" void kernel_launch(void* const* d_in, const int* in_sizes, int n_in,
                              void* d_out, int out_size)
{
    const float* freq   = (const float*)d_in[0];
    const float* ampv   = (const float*)d_in[1];
    const float* ap     = (const float*)d_in[2];
    const float* bp     = (const float*)d_in[3];
    const float* forces = (const float*)d_in[4];
    float* out = (float*)d_out;

    k_all<<<NB, 256>>>(freq, ampv, ap, bp, forces, out);
}